// round 14
// baseline (speedup 1.0000x reference)
#include <cuda_runtime.h>
#include <cuda_bf16.h>
#include <cstdint>

#define BB 4
#define NPTS 16384
#define NT 512
#define NTILES 2048

__device__ float g_T[BB * NPTS * 68];
__device__ float g_Y[BB * NPTS * 64];                 // precomputed per-point layer-1 partial
__device__ __align__(16) unsigned char g_W[94208];

// g_W source offsets (bytes)
#define BH1 0
#define BL1 11264
#define BH2 22528
#define BL2 31744
#define BH3 40960
#define BL3 50176
#define BH4 59392
#define BL4 76800
#define WBYTES 94208
// fused copies only [BH2, WBYTES): 71680 bytes; offsets within copy:
#define CPY_OFF 22528
#define CPY_BYTES 71680
#define oBH2 0
#define oBL2 9216
#define oBH3 18432
#define oBL3 27648
#define oBH4 36864
#define oBL4 54272

// fused SMEM (bytes)
#define SM_B    0          // 71680
#define SM_BIAS 71680      // 256 floats
#define SM_W1C  72704      // 5 x 64 floats (w1 cols 0,1,2,67,68)
#define SM_A1   73984      // 128 x 336B (L2/L3 activations hi|lo)
#define SM_A4   116992     // 128 x 528B (L4 input hi|lo)
#define SM_SCR  184576     // 512 floats
#define SMEM_TOTAL 186624

#define STRIDE_A1 336
#define STRIDE_A4 528

// prep dynamic smem (floats): sT 68*67 | wT 68*64 | sY 64*68
#define P_ST 0
#define P_WT 4556
#define P_SY 8908
#define PSMEM_FLOATS 13260
#define PSMEM_BYTES (PSMEM_FLOATS * 4)

__device__ __forceinline__ uint32_t smem_u32(const void* p) {
    uint32_t a;
    asm("{ .reg .u64 t; cvta.to.shared.u64 t, %1; cvt.u32.u64 %0, t; }" : "=r"(a) : "l"(p));
    return a;
}
#define GBAR(id) asm volatile("bar.sync %0, 128;" :: "r"(id) : "memory")
#define LDSM4(r0, r1, r2, r3, addr) \
    asm volatile("ldmatrix.sync.aligned.m8n8.x4.shared.b16 {%0,%1,%2,%3}, [%4];" \
                 : "=r"(r0), "=r"(r1), "=r"(r2), "=r"(r3) : "r"(addr))
#define MMA16816(c, a0, a1, a2, a3, b0, b1) \
    asm volatile("mma.sync.aligned.m16n8k16.row.col.f32.bf16.bf16.f32 " \
                 "{%0,%1,%2,%3}, {%4,%5,%6,%7}, {%8,%9}, {%0,%1,%2,%3};" \
                 : "+f"((c)[0]), "+f"((c)[1]), "+f"((c)[2]), "+f"((c)[3]) \
                 : "r"(a0), "r"(a1), "r"(a2), "r"(a3), "r"(b0), "r"(b1))

__device__ __forceinline__ uint32_t pack2(float x, float y) {
    unsigned short a = __bfloat16_as_ushort(__float2bfloat16_rn(x));
    unsigned short b = __bfloat16_as_ushort(__float2bfloat16_rn(y));
    return (uint32_t)a | ((uint32_t)b << 16);
}
__device__ __forceinline__ float lo_of(float x) {
    return x - __bfloat162float(__float2bfloat16_rn(x));
}
__device__ __forceinline__ float lrelu(float v) { return fmaxf(v, 0.1f * v); }

// ---------------- prep: transpose + Y1p GEMM (coalesced out) + weight split ----------------
__global__ void prep_kernel(const float* __restrict__ xy, const float* __restrict__ feat3d,
                            const float* __restrict__ flow3d,
                            const float* __restrict__ w1, const float* __restrict__ w2,
                            const float* __restrict__ w3, const float* __restrict__ wf) {
    extern __shared__ float psm[];
    const int blk = blockIdx.x, tid = threadIdx.x;
    if (blk < 1024) {
        float* sT = psm + P_ST;     // [c(68)][p(64)] stride 67
        float* wT = psm + P_WT;     // [k(68)][n(64)]
        float* sY = psm + P_SY;     // [p(64)][n(64)] stride 68
        const int b = blk >> 8, p0 = (blk & 255) << 6;
        const float* f3 = feat3d + (size_t)b * 64 * NPTS + p0;
#pragma unroll
        for (int it = 0; it < 16; it++) {
            int i = it * 256 + tid, c = i >> 6, pt = i & 63;
            sT[c * 67 + pt] = f3[(size_t)c * NPTS + pt];
        }
        if (tid < 128) {
            int c = tid >> 6, pt = tid & 63;
            sT[(64 + c) * 67 + pt] = flow3d[((size_t)b * 2 + c) * NPTS + p0 + pt];
            sT[(66 + c) * 67 + pt] = xy[((size_t)b * 2 + c) * NPTS + p0 + pt];
        }
        // wT: T-row index k -> w1 column {k<64: 3+k, 64:67, 65:68, 66:1, 67:2}
#pragma unroll
        for (int it = 0; it < 17; it++) {
            int i = it * 256 + tid, k = i >> 6, n = i & 63;
            int cm = (k < 64) ? (3 + k) : (k == 64) ? 67 : (k == 65) ? 68 : (k == 66) ? 1 : 2;
            wT[i] = w1[n * 69 + cm];
        }
        __syncthreads();
        // write transposed table (coalesced)
        float* dst = g_T + ((size_t)(b << 14) + p0) * 68;
#pragma unroll
        for (int it = 0; it < 17; it++) {
            int i = it * 256 + tid, pt = i / 68, c = i - pt * 68;
            dst[i] = sT[c * 67 + pt];
        }
        // Y1p: thread = (point p, output quarter n0); stage to sY
        {
            const int p = tid & 63, n0 = (tid >> 6) << 4;
            float acc[16];
#pragma unroll
            for (int j = 0; j < 16; j++) acc[j] = 0.0f;
            for (int k = 0; k < 68; k++) {
                float x = sT[k * 67 + p];
                const float4* wv = (const float4*)(wT + k * 64 + n0);
#pragma unroll
                for (int j4 = 0; j4 < 4; j4++) {
                    float4 w = wv[j4];
                    acc[j4 * 4 + 0] += x * w.x; acc[j4 * 4 + 1] += x * w.y;
                    acc[j4 * 4 + 2] += x * w.z; acc[j4 * 4 + 3] += x * w.w;
                }
            }
#pragma unroll
            for (int j4 = 0; j4 < 4; j4++)
                *(float4*)(sY + p * 68 + n0 + j4 * 4) =
                    make_float4(acc[j4 * 4], acc[j4 * 4 + 1], acc[j4 * 4 + 2], acc[j4 * 4 + 3]);
        }
        __syncthreads();
        // drain sY -> g_Y coalesced (warp writes 128B contiguous rows)
        float* yd = g_Y + ((size_t)((b << 14) + p0)) * 64;
#pragma unroll
        for (int it = 0; it < 16; it++) {
            int i = it * 256 + tid;
            yd[i] = sY[(i >> 6) * 68 + (i & 63)];
        }
    } else {
        int i = (blk - 1024) * 256 + tid;
        int n = i / 368, c = i - n * 368, l, k;
        if (c < 88)       { l = 0; k = c; }
        else if (c < 160) { l = 1; k = c - 88; }
        else if (c < 232) { l = 2; k = c - 160; }
        else              { l = 3; k = c - 232; }
        const int KR[4] = {69, 64, 64, 128}, STR[4] = {176, 144, 144, 272};
        const int BH[4] = {BH1, BH2, BH3, BH4}, BL[4] = {BL1, BL2, BL3, BL4};
        const float* src = (l == 0) ? w1 : (l == 1) ? w2 : (l == 2) ? w3 : wf;
        float v = (k < KR[l]) ? src[n * KR[l] + k] : 0.0f;
        int col = (l == 0) ? ((k < 3) ? k : k + 1) : k;
        float hf = __bfloat162float(__float2bfloat16_rn(v));
        unsigned short hb = __bfloat16_as_ushort(__float2bfloat16_rn(v));
        unsigned short lb = __bfloat16_as_ushort(__float2bfloat16_rn(v - hf));
        if (col * 2 < STR[l]) {
            int off = n * STR[l] + col * 2;
            *(unsigned short*)(g_W + BH[l] + off) = hb;
            *(unsigned short*)(g_W + BL[l] + off) = lb;
        }
    }
}

// ---------------- per-warp GEMM layer: M=32, N=16 (R9-proven) ----------------
__device__ __forceinline__ void run_layer(float* acc, uint32_t aBase, int strideA,
                                          int loAoff, int ksegs,
                                          uint32_t bHi, uint32_t bLo, int strideB,
                                          int lane, int warpPix, int nBase) {
    const int g = lane >> 3, r = lane & 7;
    const int aRow = ((g & 1) << 3) + r, aColB = (g >> 1) << 4;
    const int bRow = ((g >> 1) << 3) + r, bColB = (g & 1) << 4;
    const uint32_t aAddr = aBase + (uint32_t)(warpPix + aRow) * strideA + aColB;
    const uint32_t bhAddr = bHi + (uint32_t)(nBase + bRow) * strideB + bColB;
    const uint32_t blAddr = bLo + (uint32_t)(nBase + bRow) * strideB + bColB;
#pragma unroll
    for (int j = 0; j < ksegs; j++) {
        const uint32_t ja = (uint32_t)(j << 5);
        uint32_t Ah0[4], Ah1[4], Al0[4], Al1[4], Bh[4], Bl[4];
        LDSM4(Ah0[0], Ah0[1], Ah0[2], Ah0[3], aAddr + ja);
        LDSM4(Ah1[0], Ah1[1], Ah1[2], Ah1[3], aAddr + ja + 16u * strideA);
        LDSM4(Al0[0], Al0[1], Al0[2], Al0[3], aAddr + ja + loAoff);
        LDSM4(Al1[0], Al1[1], Al1[2], Al1[3], aAddr + ja + loAoff + 16u * strideA);
        LDSM4(Bh[0], Bh[1], Bh[2], Bh[3], bhAddr + ja);
        LDSM4(Bl[0], Bl[1], Bl[2], Bl[3], blAddr + ja);
#pragma unroll
        for (int nt = 0; nt < 2; nt++) {
            uint32_t bh0 = Bh[nt << 1], bh1 = Bh[(nt << 1) + 1];
            uint32_t bl0 = Bl[nt << 1], bl1 = Bl[(nt << 1) + 1];
            float* c0 = acc + nt * 4;
            float* c1 = acc + 8 + nt * 4;
            MMA16816(c0, Ah0[0], Ah0[1], Ah0[2], Ah0[3], bh0, bh1);
            MMA16816(c1, Ah1[0], Ah1[1], Ah1[2], Ah1[3], bh0, bh1);
            MMA16816(c0, Al0[0], Al0[1], Al0[2], Al0[3], bh0, bh1);
            MMA16816(c1, Al1[0], Al1[1], Al1[2], Al1[3], bh0, bh1);
            MMA16816(c0, Ah0[0], Ah0[1], Ah0[2], Ah0[3], bl0, bl1);
            MMA16816(c1, Ah1[0], Ah1[1], Ah1[2], Ah1[3], bl0, bl1);
        }
    }
}

__device__ __forceinline__ void epi_store(const float* acc, const float* bias,
                                          char* dst, int strideA, int loOffB,
                                          int lane, int warpPix, int nBase) {
    const int r = lane >> 2, nb = (lane & 3) << 1;
#pragma unroll
    for (int mt = 0; mt < 2; mt++) {
        char* p0 = dst + (warpPix + (mt << 4) + r) * strideA;
        char* p1 = p0 + 8 * strideA;
#pragma unroll
        for (int nt = 0; nt < 2; nt++) {
            const float* c = acc + mt * 8 + nt * 4;
            const int n = nBase + (nt << 3) + nb;
            float b0 = bias[n], b1 = bias[n + 1];
            float v00 = lrelu(c[0] + b0), v01 = lrelu(c[1] + b1);
            float v10 = lrelu(c[2] + b0), v11 = lrelu(c[3] + b1);
            *(uint32_t*)(p0 + n * 2)          = pack2(v00, v01);
            *(uint32_t*)(p0 + loOffB + n * 2) = pack2(lo_of(v00), lo_of(v01));
            *(uint32_t*)(p1 + n * 2)          = pack2(v10, v11);
            *(uint32_t*)(p1 + loOffB + n * 2) = pack2(lo_of(v10), lo_of(v11));
        }
    }
}

// ---------------- fused: identical to R13 (best fused: 119us) ----------------
__global__ __launch_bounds__(NT, 1)
void fused_kernel(const float* __restrict__ feat2d, const float* __restrict__ lf2d,
                  const int* __restrict__ nnp,
                  const float* __restrict__ w1,
                  const float* __restrict__ b1, const float* __restrict__ b2,
                  const float* __restrict__ b3, const float* __restrict__ bfin,
                  float* __restrict__ out) {
    extern __shared__ char smem[];
    const uint32_t s32 = smem_u32(smem);
    const int tid = threadIdx.x, lane = tid & 31, wid = tid >> 5;
    const int grp = wid >> 2, warpPix = grp << 5;
    const int nBase = (wid & 3) << 4;
    const int barid = 1 + grp;
    const int t = tid & 127, p32 = t & 31, q = t >> 5;
    const int prow = ((tid >> 7) << 5) + p32;

    {   // one-time: weights (L2..L4) + bias + w1 per-pixel columns
        const uint4* src = (const uint4*)(g_W + CPY_OFF);
        uint4* dst = (uint4*)(smem + SM_B);
        for (int i = tid; i < CPY_BYTES / 16; i += NT) dst[i] = src[i];
        float* sb = (float*)(smem + SM_BIAS);
        float* wc = (float*)(smem + SM_W1C);
        if (tid < 64) {
            sb[tid] = b1[tid]; sb[64 + tid] = b2[tid];
            sb[128 + tid] = b3[tid]; sb[192 + tid] = bfin[tid];
            wc[tid]       = w1[tid * 69 + 0];
            wc[64 + tid]  = w1[tid * 69 + 1];
            wc[128 + tid] = w1[tid * 69 + 2];
            wc[192 + tid] = w1[tid * 69 + 67];
            wc[256 + tid] = w1[tid * 69 + 68];
        }
    }
    __syncthreads();
    const float* sbias = (const float*)(smem + SM_BIAS);
    const float* w1c = (const float*)(smem + SM_W1C);
    float* scr = (float*)(smem + SM_SCR);

    const uint32_t aA1 = s32 + SM_A1, aA4 = s32 + SM_A4;
    const uint32_t wb = s32 + SM_B;

    for (int tile = blockIdx.x; tile < NTILES; tile += gridDim.x) {
        const int gp = (tile << 7) + prow;
        const int b = gp >> 16, pix = gp & 65535;

        // ---------- prologue ----------
        {
            const int idx = nnp[gp];
            const int pr = (b << 14) + idx;
            float av[16];
            const float* t3h = g_T + (size_t)pr * 68 + (q << 4);
#pragma unroll
            for (int k = 0; k < 16; k += 4) {
                float4 v = *(const float4*)(t3h + k);
                av[k] = v.x; av[k + 1] = v.y; av[k + 2] = v.z; av[k + 3] = v.w;
            }
            float y1p[16];
            const float4* yp = (const float4*)(g_Y + (size_t)pr * 64 + (q << 4));
#pragma unroll
            for (int j4 = 0; j4 < 4; j4++) {
                float4 v = yp[j4];
                y1p[j4 * 4] = v.x; y1p[j4 * 4 + 1] = v.y;
                y1p[j4 * 4 + 2] = v.z; y1p[j4 * 4 + 3] = v.w;
            }
            const float* lf = lf2d + (((size_t)b * 2) << 16) + pix;
            const float lfx = lf[0], lfy = lf[65536];

            char* A4p = smem + SM_A4 + prow * STRIDE_A4;
            const float* f2p = feat2d + (((size_t)(b * 64 + (q << 4))) << 16) + pix;
            float pc = 0.0f;
#pragma unroll
            for (int c = 0; c < 16; c += 2) {
                float v0 = f2p[(size_t)c << 16], v1 = f2p[(size_t)(c + 1) << 16];
                pc += av[c] * v0 + av[c + 1] * v1;
                *(uint32_t*)(A4p + 128 + (q << 5) + c * 2) = pack2(v0, v1);
                *(uint32_t*)(A4p + 384 + (q << 5) + c * 2) = pack2(lo_of(v0), lo_of(v1));
            }
            scr[tid] = pc;
            GBAR(barid);
            const int b0i = (grp << 7) + p32;
            const float corr = (scr[b0i] + scr[b0i + 32] + scr[b0i + 64] + scr[b0i + 96])
                               * (1.0f / 64.0f);
            const float swi = -(float)(pix & 255), shi = -(float)(pix >> 8);

            char* A1p = smem + SM_A1 + prow * STRIDE_A1;
#pragma unroll
            for (int j = 0; j < 16; j += 2) {
                const int c = (q << 4) + j;
                float ya = y1p[j]     + corr * w1c[c]     + swi * w1c[64 + c]
                         + shi * w1c[128 + c]     - lfx * w1c[192 + c]
                         - lfy * w1c[256 + c]     + sbias[c];
                float yb = y1p[j + 1] + corr * w1c[c + 1] + swi * w1c[64 + c + 1]
                         + shi * w1c[128 + c + 1] - lfx * w1c[192 + c + 1]
                         - lfy * w1c[256 + c + 1] + sbias[c + 1];
                ya = lrelu(ya); yb = lrelu(yb);
                *(uint32_t*)(A1p + c * 2)       = pack2(ya, yb);
                *(uint32_t*)(A1p + 128 + c * 2) = pack2(lo_of(ya), lo_of(yb));
            }
        }
        GBAR(barid);

        float acc[16];

        // ---- layer 2: A1 -> A1 ----
#pragma unroll
        for (int i = 0; i < 16; i++) acc[i] = 0.0f;
        run_layer(acc, aA1, STRIDE_A1, 128, 4,
                  wb + oBH2, wb + oBL2, 144, lane, warpPix, nBase);
        GBAR(barid);
        epi_store(acc, sbias + 64, smem + SM_A1, STRIDE_A1, 128, lane, warpPix, nBase);
        GBAR(barid);

        // ---- layer 3: A1 -> A4 ----
#pragma unroll
        for (int i = 0; i < 16; i++) acc[i] = 0.0f;
        run_layer(acc, aA1, STRIDE_A1, 128, 4,
                  wb + oBH3, wb + oBL3, 144, lane, warpPix, nBase);
        epi_store(acc, sbias + 128, smem + SM_A4, STRIDE_A4, 256, lane, warpPix, nBase);
        GBAR(barid);

        // ---- layer 4: K=128 from A4 ----
#pragma unroll
        for (int i = 0; i < 16; i++) acc[i] = 0.0f;
        run_layer(acc, aA4, STRIDE_A4, 256, 8,
                  wb + oBH4, wb + oBL4, 272, lane, warpPix, nBase);

        // ---- output: direct STG ----
        {
            const int pixbase = (tile << 7) & 65535;
            const int r = lane >> 2, nb = (lane & 3) << 1;
            float* ob = out + ((size_t)b << 22) + pixbase;
#pragma unroll
            for (int mt = 0; mt < 2; mt++) {
                float* p0 = ob + warpPix + (mt << 4) + r;
                float* p1 = p0 + 8;
#pragma unroll
                for (int nt = 0; nt < 2; nt++) {
                    const float* c = acc + mt * 8 + nt * 4;
                    const int n = nBase + (nt << 3) + nb;
                    float bb0 = sbias[192 + n], bb1 = sbias[192 + n + 1];
                    p0[(size_t)n << 16] = lrelu(c[0] + bb0);
                    p0[(size_t)(n + 1) << 16] = lrelu(c[1] + bb1);
                    p1[(size_t)n << 16] = lrelu(c[2] + bb0);
                    p1[(size_t)(n + 1) << 16] = lrelu(c[3] + bb1);
                }
            }
        }
        GBAR(barid);
    }
}

extern "C" void kernel_launch(void* const* d_in, const int* in_sizes, int n_in,
                              void* d_out, int out_size) {
    const float* xy   = (const float*)d_in[0];
    const float* f2d  = (const float*)d_in[1];
    const float* f3d  = (const float*)d_in[2];
    const float* lf2d = (const float*)d_in[3];
    const float* lf3d = (const float*)d_in[4];
    const int*   nnp  = (const int*)d_in[5];
    const float* w1 = (const float*)d_in[6];
    const float* b1 = (const float*)d_in[7];
    const float* w2 = (const float*)d_in[8];
    const float* b2 = (const float*)d_in[9];
    const float* w3 = (const float*)d_in[10];
    const float* b3 = (const float*)d_in[11];
    const float* wf = (const float*)d_in[12];
    const float* bf = (const float*)d_in[13];
    float* out = (float*)d_out;

    cudaFuncSetAttribute(prep_kernel,
                         cudaFuncAttributeMaxDynamicSharedMemorySize, PSMEM_BYTES);
    cudaFuncSetAttribute(fused_kernel,
                         cudaFuncAttributeMaxDynamicSharedMemorySize, SMEM_TOTAL);
    prep_kernel<<<1024 + 92, 256, PSMEM_BYTES>>>(xy, f3d, lf3d, w1, w2, w3, wf);
    fused_kernel<<<148, NT, SMEM_TOTAL>>>(f2d, lf2d, nnp, w1, b1, b2, b3, bf, out);
}

// round 15
// speedup vs baseline: 1.0310x; 1.0310x over previous
#include <cuda_runtime.h>
#include <cuda_bf16.h>
#include <cstdint>

#define BB 4
#define NPTS 16384
#define NT 512
#define NTILES 2048

__device__ float g_T[BB * NPTS * 68];
__device__ float g_Y[BB * NPTS * 64];                 // per-point layer-1 partial (tensor-core)
__device__ __align__(16) unsigned char g_W[94208];

// g_W offsets (bytes)
#define BH1 0
#define BL1 11264
#define BH2 22528
#define BL2 31744
#define BH3 40960
#define BL3 50176
#define BH4 59392
#define BL4 76800
#define WBYTES 94208
// fused copies only [BH2, WBYTES)
#define CPY_OFF 22528
#define CPY_BYTES 71680
#define oBH2 0
#define oBL2 9216
#define oBH3 18432
#define oBL3 27648
#define oBH4 36864
#define oBL4 54272

// fused SMEM (bytes)
#define SM_B    0          // 71680
#define SM_BIAS 71680      // 256 floats
#define SM_W1C  72704      // 5 x 64 floats (w1 cols 0,1,2,67,68)
#define SM_A1   73984      // 128 x 336B
#define SM_A4   116992     // 128 x 528B
#define SM_SCR  184576     // 512 floats
#define SMEM_TOTAL 186624

#define STRIDE_A1 336
#define STRIDE_A4 528

// points-kernel dynamic smem (bytes): sT/sY union | A-tile | B1 copy
#define Q_ST   0                   // 68*67 floats = 18224B (sY 64*68*4=17408 fits under)
#define Q_AT   18224               // 64 x 336B = 21504
#define Q_B1   39728               // 22528B (BH1|BL1)
#define QSMEM  62256

__device__ __forceinline__ uint32_t smem_u32(const void* p) {
    uint32_t a;
    asm("{ .reg .u64 t; cvta.to.shared.u64 t, %1; cvt.u32.u64 %0, t; }" : "=r"(a) : "l"(p));
    return a;
}
#define GBAR(id) asm volatile("bar.sync %0, 128;" :: "r"(id) : "memory")
#define LDSM4(r0, r1, r2, r3, addr) \
    asm volatile("ldmatrix.sync.aligned.m8n8.x4.shared.b16 {%0,%1,%2,%3}, [%4];" \
                 : "=r"(r0), "=r"(r1), "=r"(r2), "=r"(r3) : "r"(addr))
#define MMA16816(c, a0, a1, a2, a3, b0, b1) \
    asm volatile("mma.sync.aligned.m16n8k16.row.col.f32.bf16.bf16.f32 " \
                 "{%0,%1,%2,%3}, {%4,%5,%6,%7}, {%8,%9}, {%0,%1,%2,%3};" \
                 : "+f"((c)[0]), "+f"((c)[1]), "+f"((c)[2]), "+f"((c)[3]) \
                 : "r"(a0), "r"(a1), "r"(a2), "r"(a3), "r"(b0), "r"(b1))

__device__ __forceinline__ uint32_t pack2(float x, float y) {
    unsigned short a = __bfloat16_as_ushort(__float2bfloat16_rn(x));
    unsigned short b = __bfloat16_as_ushort(__float2bfloat16_rn(y));
    return (uint32_t)a | ((uint32_t)b << 16);
}
__device__ __forceinline__ float lo_of(float x) {
    return x - __bfloat162float(__float2bfloat16_rn(x));
}
__device__ __forceinline__ float lrelu(float v) { return fmaxf(v, 0.1f * v); }

// ---------------- shared per-warp GEMM: M=32 rows, N=16 cols ----------------
__device__ __forceinline__ void run_layer(float* acc, uint32_t aBase, int strideA,
                                          int loAoff, int ksegs,
                                          uint32_t bHi, uint32_t bLo, int strideB,
                                          int lane, int warpPix, int nBase) {
    const int g = lane >> 3, r = lane & 7;
    const int aRow = ((g & 1) << 3) + r, aColB = (g >> 1) << 4;
    const int bRow = ((g >> 1) << 3) + r, bColB = (g & 1) << 4;
    const uint32_t aAddr = aBase + (uint32_t)(warpPix + aRow) * strideA + aColB;
    const uint32_t bhAddr = bHi + (uint32_t)(nBase + bRow) * strideB + bColB;
    const uint32_t blAddr = bLo + (uint32_t)(nBase + bRow) * strideB + bColB;
#pragma unroll
    for (int j = 0; j < ksegs; j++) {
        const uint32_t ja = (uint32_t)(j << 5);
        uint32_t Ah0[4], Ah1[4], Al0[4], Al1[4], Bh[4], Bl[4];
        LDSM4(Ah0[0], Ah0[1], Ah0[2], Ah0[3], aAddr + ja);
        LDSM4(Ah1[0], Ah1[1], Ah1[2], Ah1[3], aAddr + ja + 16u * strideA);
        LDSM4(Al0[0], Al0[1], Al0[2], Al0[3], aAddr + ja + loAoff);
        LDSM4(Al1[0], Al1[1], Al1[2], Al1[3], aAddr + ja + loAoff + 16u * strideA);
        LDSM4(Bh[0], Bh[1], Bh[2], Bh[3], bhAddr + ja);
        LDSM4(Bl[0], Bl[1], Bl[2], Bl[3], blAddr + ja);
#pragma unroll
        for (int nt = 0; nt < 2; nt++) {
            uint32_t bh0 = Bh[nt << 1], bh1 = Bh[(nt << 1) + 1];
            uint32_t bl0 = Bl[nt << 1], bl1 = Bl[(nt << 1) + 1];
            float* c0 = acc + nt * 4;
            float* c1 = acc + 8 + nt * 4;
            MMA16816(c0, Ah0[0], Ah0[1], Ah0[2], Ah0[3], bh0, bh1);
            MMA16816(c1, Ah1[0], Ah1[1], Ah1[2], Ah1[3], bh0, bh1);
            MMA16816(c0, Al0[0], Al0[1], Al0[2], Al0[3], bh0, bh1);
            MMA16816(c1, Al1[0], Al1[1], Al1[2], Al1[3], bh0, bh1);
            MMA16816(c0, Ah0[0], Ah0[1], Ah0[2], Ah0[3], bl0, bl1);
            MMA16816(c1, Ah1[0], Ah1[1], Ah1[2], Ah1[3], bl0, bl1);
        }
    }
}

__device__ __forceinline__ void epi_store(const float* acc, const float* bias,
                                          char* dst, int strideA, int loOffB,
                                          int lane, int warpPix, int nBase) {
    const int r = lane >> 2, nb = (lane & 3) << 1;
#pragma unroll
    for (int mt = 0; mt < 2; mt++) {
        char* p0 = dst + (warpPix + (mt << 4) + r) * strideA;
        char* p1 = p0 + 8 * strideA;
#pragma unroll
        for (int nt = 0; nt < 2; nt++) {
            const float* c = acc + mt * 8 + nt * 4;
            const int n = nBase + (nt << 3) + nb;
            float b0 = bias[n], b1 = bias[n + 1];
            float v00 = lrelu(c[0] + b0), v01 = lrelu(c[1] + b1);
            float v10 = lrelu(c[2] + b0), v11 = lrelu(c[3] + b1);
            *(uint32_t*)(p0 + n * 2)          = pack2(v00, v01);
            *(uint32_t*)(p0 + loOffB + n * 2) = pack2(lo_of(v00), lo_of(v01));
            *(uint32_t*)(p1 + n * 2)          = pack2(v10, v11);
            *(uint32_t*)(p1 + loOffB + n * 2) = pack2(lo_of(v10), lo_of(v11));
        }
    }
}

// ---------------- kernel A: weight split (must run first) ----------------
__global__ void wsplit_kernel(const float* __restrict__ w1, const float* __restrict__ w2,
                              const float* __restrict__ w3, const float* __restrict__ wf) {
    int i = blockIdx.x * 256 + threadIdx.x;   // 0..23551 = n*368 + c
    int n = i / 368, c = i - n * 368, l, k;
    if (c < 88)       { l = 0; k = c; }
    else if (c < 160) { l = 1; k = c - 88; }
    else if (c < 232) { l = 2; k = c - 160; }
    else              { l = 3; k = c - 232; }
    const int KR[4] = {69, 64, 64, 128}, STR[4] = {176, 144, 144, 272};
    const int BHo[4] = {BH1, BH2, BH3, BH4}, BLo[4] = {BL1, BL2, BL3, BL4};
    const float* src = (l == 0) ? w1 : (l == 1) ? w2 : (l == 2) ? w3 : wf;
    float v = (k < KR[l]) ? src[n * KR[l] + k] : 0.0f;
    int col = (l == 0) ? ((k < 3) ? k : k + 1) : k;
    float hf = __bfloat162float(__float2bfloat16_rn(v));
    unsigned short hb = __bfloat16_as_ushort(__float2bfloat16_rn(v));
    unsigned short lb = __bfloat16_as_ushort(__float2bfloat16_rn(v - hf));
    if (col * 2 < STR[l]) {
        int off = n * STR[l] + col * 2;
        *(unsigned short*)(g_W + BHo[l] + off) = hb;
        *(unsigned short*)(g_W + BLo[l] + off) = lb;
    }
}

// ---------------- kernel B: transpose + tensor-core Y1p ----------------
// A-tile column map (matches w1 col layout in BH1): col1<-xy_x(T66), col2<-xy_y(T67),
// col4+k<-feat_k(Tk), col68<-fl_x(T64), col69<-fl_y(T65), others 0.
__global__ __launch_bounds__(256, 1)
void points_kernel(const float* __restrict__ xy, const float* __restrict__ feat3d,
                   const float* __restrict__ flow3d) {
    extern __shared__ float psm[];
    float* sT = psm + 0;                       // [c(68)][p(64)] stride 67
    char* sA = (char*)psm + Q_AT;              // 64 x 336B split-bf16 A-tile
    char* sB = (char*)psm + Q_B1;              // BH1|BL1 copy
    float* sY = psm + 0;                       // reuse sT region after A-tile built
    const uint32_t s32 = smem_u32(psm);
    const int tid = threadIdx.x, lane = tid & 31, wid = tid >> 5;
    const int blk = blockIdx.x;
    const int b = blk >> 8, p0 = (blk & 255) << 6;

    // load sT (coalesced)
    const float* f3 = feat3d + (size_t)b * 64 * NPTS + p0;
#pragma unroll
    for (int it = 0; it < 16; it++) {
        int i = it * 256 + tid, c = i >> 6, pt = i & 63;
        sT[c * 67 + pt] = f3[(size_t)c * NPTS + pt];
    }
    if (tid < 128) {
        int c = tid >> 6, pt = tid & 63;
        sT[(64 + c) * 67 + pt] = flow3d[((size_t)b * 2 + c) * NPTS + p0 + pt];
        sT[(66 + c) * 67 + pt] = xy[((size_t)b * 2 + c) * NPTS + p0 + pt];
    }
    // copy w1 split weights (BH1|BL1 = 22528B)
    {
        const uint4* src = (const uint4*)g_W;
        uint4* dst = (uint4*)sB;
        for (int i = tid; i < 22528 / 16; i += 256) dst[i] = src[i];
    }
    __syncthreads();

    // write g_T (coalesced)
    float* dstT = g_T + ((size_t)(b << 14) + p0) * 68;
#pragma unroll
    for (int it = 0; it < 17; it++) {
        int i = it * 256 + tid, pt = i / 68, c = i - pt * 68;
        dstT[i] = sT[c * 67 + pt];
    }

    // build A-tile: thread = (px = tid&63, colgroup = tid>>6 -> 20 cols)
    {
        const int px = tid & 63, cg = tid >> 6;
        char* Ap = sA + px * STRIDE_A1;
#pragma unroll
        for (int cc = 0; cc < 20; cc += 2) {
            const int c0 = cg * 20 + cc, c1 = c0 + 1;
            float v0, v1;
            v0 = (c0 == 1) ? sT[66 * 67 + px] : (c0 == 2) ? sT[67 * 67 + px]
               : (c0 >= 4 && c0 < 68) ? sT[(c0 - 4) * 67 + px]
               : (c0 == 68) ? sT[64 * 67 + px] : (c0 == 69) ? sT[65 * 67 + px] : 0.0f;
            v1 = (c1 == 1) ? sT[66 * 67 + px] : (c1 == 2) ? sT[67 * 67 + px]
               : (c1 >= 4 && c1 < 68) ? sT[(c1 - 4) * 67 + px]
               : (c1 == 68) ? sT[64 * 67 + px] : (c1 == 69) ? sT[65 * 67 + px] : 0.0f;
            *(uint32_t*)(Ap + c0 * 2)       = pack2(v0, v1);
            *(uint32_t*)(Ap + 160 + c0 * 2) = pack2(lo_of(v0), lo_of(v1));
        }
    }
    __syncthreads();

    // Y1p GEMM: 8 warps = 2 groups(32px) x 4 N-quarters, K=80 (ksegs=5)
    float acc[16];
#pragma unroll
    for (int i = 0; i < 16; i++) acc[i] = 0.0f;
    const int grp = wid >> 2, warpPix = grp << 5, nBase = (wid & 3) << 4;
    run_layer(acc, s32 + Q_AT, STRIDE_A1, 160, 5,
              s32 + Q_B1, s32 + Q_B1 + 11264, 176, lane, warpPix, nBase);
    __syncthreads();   // sT reads done (A-build) -> safe to overwrite sY region

    // stage acc -> sY (stride 68), then coalesced drain
    {
        const int r = lane >> 2, nb = (lane & 3) << 1;
#pragma unroll
        for (int mt = 0; mt < 2; mt++) {
            float* q0 = sY + (warpPix + (mt << 4) + r) * 68;
            float* q1 = q0 + 8 * 68;
#pragma unroll
            for (int nt = 0; nt < 2; nt++) {
                const float* c = acc + mt * 8 + nt * 4;
                const int n = nBase + (nt << 3) + nb;
                q0[n] = c[0]; q0[n + 1] = c[1];
                q1[n] = c[2]; q1[n + 1] = c[3];
            }
        }
    }
    __syncthreads();
    float* yd = g_Y + ((size_t)((b << 14) + p0)) * 64;
#pragma unroll
    for (int it = 0; it < 16; it++) {
        int i = it * 256 + tid;
        yd[i] = sY[(i >> 6) * 68 + (i & 63)];
    }
}

// ---------------- fused: identical to R13/R14 (best fused: ~119-120us ncu) ----------------
__global__ __launch_bounds__(NT, 1)
void fused_kernel(const float* __restrict__ feat2d, const float* __restrict__ lf2d,
                  const int* __restrict__ nnp,
                  const float* __restrict__ w1,
                  const float* __restrict__ b1, const float* __restrict__ b2,
                  const float* __restrict__ b3, const float* __restrict__ bfin,
                  float* __restrict__ out) {
    extern __shared__ char smem[];
    const uint32_t s32 = smem_u32(smem);
    const int tid = threadIdx.x, lane = tid & 31, wid = tid >> 5;
    const int grp = wid >> 2, warpPix = grp << 5;
    const int nBase = (wid & 3) << 4;
    const int barid = 1 + grp;
    const int t = tid & 127, p32 = t & 31, q = t >> 5;
    const int prow = ((tid >> 7) << 5) + p32;

    {
        const uint4* src = (const uint4*)(g_W + CPY_OFF);
        uint4* dst = (uint4*)(smem + SM_B);
        for (int i = tid; i < CPY_BYTES / 16; i += NT) dst[i] = src[i];
        float* sb = (float*)(smem + SM_BIAS);
        float* wc = (float*)(smem + SM_W1C);
        if (tid < 64) {
            sb[tid] = b1[tid]; sb[64 + tid] = b2[tid];
            sb[128 + tid] = b3[tid]; sb[192 + tid] = bfin[tid];
            wc[tid]       = w1[tid * 69 + 0];
            wc[64 + tid]  = w1[tid * 69 + 1];
            wc[128 + tid] = w1[tid * 69 + 2];
            wc[192 + tid] = w1[tid * 69 + 67];
            wc[256 + tid] = w1[tid * 69 + 68];
        }
    }
    __syncthreads();
    const float* sbias = (const float*)(smem + SM_BIAS);
    const float* w1c = (const float*)(smem + SM_W1C);
    float* scr = (float*)(smem + SM_SCR);

    const uint32_t aA1 = s32 + SM_A1, aA4 = s32 + SM_A4;
    const uint32_t wb = s32 + SM_B;

    for (int tile = blockIdx.x; tile < NTILES; tile += gridDim.x) {
        const int gp = (tile << 7) + prow;
        const int b = gp >> 16, pix = gp & 65535;

        {
            const int idx = nnp[gp];
            const int pr = (b << 14) + idx;
            float av[16];
            const float* t3h = g_T + (size_t)pr * 68 + (q << 4);
#pragma unroll
            for (int k = 0; k < 16; k += 4) {
                float4 v = *(const float4*)(t3h + k);
                av[k] = v.x; av[k + 1] = v.y; av[k + 2] = v.z; av[k + 3] = v.w;
            }
            float y1p[16];
            const float4* yp = (const float4*)(g_Y + (size_t)pr * 64 + (q << 4));
#pragma unroll
            for (int j4 = 0; j4 < 4; j4++) {
                float4 v = yp[j4];
                y1p[j4 * 4] = v.x; y1p[j4 * 4 + 1] = v.y;
                y1p[j4 * 4 + 2] = v.z; y1p[j4 * 4 + 3] = v.w;
            }
            const float* lf = lf2d + (((size_t)b * 2) << 16) + pix;
            const float lfx = lf[0], lfy = lf[65536];

            char* A4p = smem + SM_A4 + prow * STRIDE_A4;
            const float* f2p = feat2d + (((size_t)(b * 64 + (q << 4))) << 16) + pix;
            float pc = 0.0f;
#pragma unroll
            for (int c = 0; c < 16; c += 2) {
                float v0 = f2p[(size_t)c << 16], v1 = f2p[(size_t)(c + 1) << 16];
                pc += av[c] * v0 + av[c + 1] * v1;
                *(uint32_t*)(A4p + 128 + (q << 5) + c * 2) = pack2(v0, v1);
                *(uint32_t*)(A4p + 384 + (q << 5) + c * 2) = pack2(lo_of(v0), lo_of(v1));
            }
            scr[tid] = pc;
            GBAR(barid);
            const int b0i = (grp << 7) + p32;
            const float corr = (scr[b0i] + scr[b0i + 32] + scr[b0i + 64] + scr[b0i + 96])
                               * (1.0f / 64.0f);
            const float swi = -(float)(pix & 255), shi = -(float)(pix >> 8);

            char* A1p = smem + SM_A1 + prow * STRIDE_A1;
#pragma unroll
            for (int j = 0; j < 16; j += 2) {
                const int c = (q << 4) + j;
                float ya = y1p[j]     + corr * w1c[c]     + swi * w1c[64 + c]
                         + shi * w1c[128 + c]     - lfx * w1c[192 + c]
                         - lfy * w1c[256 + c]     + sbias[c];
                float yb = y1p[j + 1] + corr * w1c[c + 1] + swi * w1c[64 + c + 1]
                         + shi * w1c[128 + c + 1] - lfx * w1c[192 + c + 1]
                         - lfy * w1c[256 + c + 1] + sbias[c + 1];
                ya = lrelu(ya); yb = lrelu(yb);
                *(uint32_t*)(A1p + c * 2)       = pack2(ya, yb);
                *(uint32_t*)(A1p + 128 + c * 2) = pack2(lo_of(ya), lo_of(yb));
            }
        }
        GBAR(barid);

        float acc[16];

        // ---- layer 2 ----
#pragma unroll
        for (int i = 0; i < 16; i++) acc[i] = 0.0f;
        run_layer(acc, aA1, STRIDE_A1, 128, 4,
                  wb + oBH2, wb + oBL2, 144, lane, warpPix, nBase);
        GBAR(barid);
        epi_store(acc, sbias + 64, smem + SM_A1, STRIDE_A1, 128, lane, warpPix, nBase);
        GBAR(barid);

        // ---- layer 3 ----
#pragma unroll
        for (int i = 0; i < 16; i++) acc[i] = 0.0f;
        run_layer(acc, aA1, STRIDE_A1, 128, 4,
                  wb + oBH3, wb + oBL3, 144, lane, warpPix, nBase);
        epi_store(acc, sbias + 128, smem + SM_A4, STRIDE_A4, 256, lane, warpPix, nBase);
        GBAR(barid);

        // ---- layer 4 ----
#pragma unroll
        for (int i = 0; i < 16; i++) acc[i] = 0.0f;
        run_layer(acc, aA4, STRIDE_A4, 256, 8,
                  wb + oBH4, wb + oBL4, 272, lane, warpPix, nBase);

        {
            const int pixbase = (tile << 7) & 65535;
            const int r = lane >> 2, nb = (lane & 3) << 1;
            float* ob = out + ((size_t)b << 22) + pixbase;
#pragma unroll
            for (int mt = 0; mt < 2; mt++) {
                float* p0 = ob + warpPix + (mt << 4) + r;
                float* p1 = p0 + 8;
#pragma unroll
                for (int nt = 0; nt < 2; nt++) {
                    const float* c = acc + mt * 8 + nt * 4;
                    const int n = nBase + (nt << 3) + nb;
                    float bb0 = sbias[192 + n], bb1 = sbias[192 + n + 1];
                    p0[(size_t)n << 16] = lrelu(c[0] + bb0);
                    p0[(size_t)(n + 1) << 16] = lrelu(c[1] + bb1);
                    p1[(size_t)n << 16] = lrelu(c[2] + bb0);
                    p1[(size_t)(n + 1) << 16] = lrelu(c[3] + bb1);
                }
            }
        }
        GBAR(barid);
    }
}

extern "C" void kernel_launch(void* const* d_in, const int* in_sizes, int n_in,
                              void* d_out, int out_size) {
    const float* xy   = (const float*)d_in[0];
    const float* f2d  = (const float*)d_in[1];
    const float* f3d  = (const float*)d_in[2];
    const float* lf2d = (const float*)d_in[3];
    const float* lf3d = (const float*)d_in[4];
    const int*   nnp  = (const int*)d_in[5];
    const float* w1 = (const float*)d_in[6];
    const float* b1 = (const float*)d_in[7];
    const float* w2 = (const float*)d_in[8];
    const float* b2 = (const float*)d_in[9];
    const float* w3 = (const float*)d_in[10];
    const float* b3 = (const float*)d_in[11];
    const float* wf = (const float*)d_in[12];
    const float* bf = (const float*)d_in[13];
    float* out = (float*)d_out;

    cudaFuncSetAttribute(points_kernel,
                         cudaFuncAttributeMaxDynamicSharedMemorySize, QSMEM);
    cudaFuncSetAttribute(fused_kernel,
                         cudaFuncAttributeMaxDynamicSharedMemorySize, SMEM_TOTAL);
    wsplit_kernel<<<92, 256>>>(w1, w2, w3, wf);
    points_kernel<<<1024, 256, QSMEM>>>(xy, f3d, lf3d);
    fused_kernel<<<148, NT, SMEM_TOTAL>>>(f2d, lf2d, nnp, w1, b1, b2, b3, bf, out);
}